// round 7
// baseline (speedup 1.0000x reference)
#include <cuda_runtime.h>
#include <cuda_fp16.h>
#include <cstdint>

#define NB      256          // N_RES * EXPR flattened rows
#define NC      1025         // coeffs per row
#define NF      128          // frames
#define HOP     1024
#define NSAMP   131072
#define FPB     16           // frames per ifft block
#define NCHUNK  (NF / FPB)   // 8

// Scratch (allowed: __device__ globals, no runtime alloc)
__device__ __half2 g_spec[33587200];     // NB*NF*NC fp16 spectrum, 134MB

// ---------------------------------------------------------------------------
// Threefry-2x32 (20 rounds), JAX partitionable counter mode: key=(0,42),
// x=(0, i), output = v0 ^ v1.   (bit-verified in round 2)
// ---------------------------------------------------------------------------
__device__ __forceinline__ uint32_t threefry_xor(uint32_t x0, uint32_t x1) {
    const uint32_t ks0 = 0u, ks1 = 42u;
    const uint32_t ks2 = ks0 ^ ks1 ^ 0x1BD11BDAu;
    x0 += ks0; x1 += ks1;
#define TF_R(r) { x0 += x1; x1 = __funnelshift_l(x1, x1, (r)); x1 ^= x0; }
    TF_R(13) TF_R(15) TF_R(26) TF_R(6)
    x0 += ks1; x1 += ks2 + 1u;
    TF_R(17) TF_R(29) TF_R(16) TF_R(24)
    x0 += ks2; x1 += ks0 + 2u;
    TF_R(13) TF_R(15) TF_R(26) TF_R(6)
    x0 += ks0; x1 += ks1 + 3u;
    TF_R(17) TF_R(29) TF_R(16) TF_R(24)
    x0 += ks1; x1 += ks2 + 4u;
    TF_R(13) TF_R(15) TF_R(26) TF_R(6)
    x0 += ks2; x1 += ks0 + 5u;
#undef TF_R
    return x0 ^ x1;
}

// ---------------------------------------------------------------------------
// Kernel 1: spectrum synthesis
// ---------------------------------------------------------------------------
__global__ void __launch_bounds__(256) spec_kernel(
    const float* __restrict__ amp,   const float* __restrict__ phase,
    const float* __restrict__ decay, const float* __restrict__ dith)
{
    int gid = blockIdx.x * 256 + threadIdx.x;
    if (gid >= NB * NC) return;
    int b = gid / NC;
    int k = gid - b * NC;
    int pidx = (((b >> 2) * NC + k) << 2) + (b & 3);   // (N_RES, NC, EXPR) layout

    float a  = amp[pidx];
    float ph = phase[pidx];
    float dc = decay[pidx];
    float dt = dith[pidx];

    float sig = 1.0f / (1.0f + expf(-dc));
    float c   = 0.5f + (sig * 0.5f) * 0.99f;
    float m   = a * a;
    float sp  = tanhf(ph) * 3.14159274101257324f;
    float d   = tanhf(dt);

    uint32_t idx = (uint32_t)(b * NF) * (uint32_t)NC + (uint32_t)k;
    float acc = 0.0f;
    __half2* __restrict__ outp = g_spec + idx;

    #pragma unroll 4
    for (int t = 0; t < NF; t++) {
        uint32_t bits = threefry_xor(0u, idx);
        float u  = __uint_as_float((bits >> 9) | 0x3f800000u) - 1.0f;  // [0,1)
        float nz = fmaf(u, 2.0f, -1.0f);                               // [-1,1)
        acc += fmaf(d, nz, sp);
        m   *= c;

        float kq  = rintf(acc * 0.15915494309189535f);
        float red = fmaf(kq, -6.2831854820251465f, acc);
        red       = fmaf(kq,  1.7484555e-07f, red);
        float sn, cs;
        __sincosf(red, &sn, &cs);

        *outp = __floats2half2_rn(m * cs, m * sn);
        outp += NC;
        idx  += NC;
    }
}

// ---------------------------------------------------------------------------
// complex helpers
// ---------------------------------------------------------------------------
__device__ __forceinline__ float2 cadd(float2 a, float2 b){ return make_float2(a.x+b.x, a.y+b.y); }
__device__ __forceinline__ float2 csub(float2 a, float2 b){ return make_float2(a.x-b.x, a.y-b.y); }
__device__ __forceinline__ float2 cmul(float2 a, float2 b){
    return make_float2(a.x*b.x - a.y*b.y, a.x*b.y + a.y*b.x);
}
__device__ __forceinline__ float2 cmulc(float2 a, float cx, float cy){
    return make_float2(a.x*cx - a.y*cy, a.x*cy + a.y*cx);
}

__device__ __forceinline__ void radix4_inv(float2 a, float2 b, float2 c, float2 d,
                                           float2& t0, float2& t1, float2& t2, float2& t3)
{
    float2 apc = cadd(a, c), amc = csub(a, c);
    float2 bpd = cadd(b, d), bmd = csub(b, d);
    t0 = cadd(apc, bpd);
    t2 = csub(apc, bpd);
    t1 = make_float2(amc.x - bmd.y, amc.y + bmd.x);  // (a-c) + i(b-d)
    t3 = make_float2(amc.x + bmd.y, amc.y - bmd.x);  // (a-c) - i(b-d)
}

// W16^e = e^{+2pi i e/16} tables (e up to 9)
__device__ __constant__ float WC16[10] = {1.0f, 0.9238795325f, 0.7071067812f, 0.3826834324f,
                                          0.0f, 0.0f, -0.7071067812f, 0.0f, 0.0f, -0.9238795325f};
__device__ __constant__ float WS16[10] = {0.0f, 0.3826834324f, 0.7071067812f, 0.9238795325f,
                                          1.0f, 0.0f,  0.7071067812f, 0.0f, 0.0f, -0.3826834324f};

// Layer 1 of inverse 16-pt DFT, IN PLACE on v[16] (each n0-group reads and
// writes the same four slots; groups are disjoint).
__device__ __forceinline__ void dft16_layer1(float2 v[16])
{
    #pragma unroll
    for (int n0 = 0; n0 < 4; n0++) {
        float2 a0, a1, a2, a3;
        radix4_inv(v[n0], v[n0+4], v[n0+8], v[n0+12], a0, a1, a2, a3);
        v[n0]      = a0;
        v[4  + n0] = (n0 == 0) ? a1 : cmulc(a1, WC16[n0],   WS16[n0]);
        v[8  + n0] = (n0 == 0) ? a2 : cmulc(a2, WC16[2*n0], WS16[2*n0]);
        v[12 + n0] = (n0 == 0) ? a3 : cmulc(a3, WC16[3*n0], WS16[3*n0]);
    }
}

// e^{i pi j/16}, j = 0..15 (fold twiddle per-j factor; folds to immediates)
__device__ __forceinline__ float2 fj_const(int j)
{
    const float fc[16] = { 1.0f, 0.9807852804f, 0.9238795325f, 0.8314696123f,
                           0.7071067812f, 0.5555702330f, 0.3826834324f, 0.1950903220f,
                           0.0f, -0.1950903220f, -0.3826834324f, -0.5555702330f,
                          -0.7071067812f, -0.8314696123f, -0.9238795325f, -0.9807852804f };
    const float fs[16] = { 0.0f, 0.1950903220f, 0.3826834324f, 0.5555702330f,
                           0.7071067812f, 0.8314696123f, 0.9238795325f, 0.9807852804f,
                           1.0f, 0.9807852804f, 0.9238795325f, 0.8314696123f,
                           0.7071067812f, 0.5555702330f, 0.3826834324f, 0.1950903220f };
    return make_float2(fc[j], fs[j]);
}

// XOR stagger: phys(L) = L ^ ((L>>4)&15) — conflict-free for all phases here.
// Note STAG(L + 256) == STAG(L) + 256 (bit 8 doesn't feed the XOR).
#define STAG(L) ((L) ^ (((L) >> 4) & 15))

// ---------------------------------------------------------------------------
// Kernel 2: fused irfft + overlap-add, radix-16, register-slimmed:
// layer 2 of each dft16 is fused with the twiddled smem store (y[16] never
// materialized); layer 1 runs in place on v[16].
// ---------------------------------------------------------------------------
__global__ void __launch_bounds__(64, 8) ifft_ola_kernel(float2* __restrict__ out2)
{
    __shared__ float2 buf[1024];

    const int t       = threadIdx.x;          // 0..63
    const int b       = blockIdx.y;
    const int chunk   = blockIdx.x;
    const int t_start = chunk * FPB;
    const int t_first = (chunk == 0) ? 0 : t_start - 1;

    // hoisted frame-invariant twiddles
    float sb, cb;
    __sincosf((float)t * (3.14159265358979f / 1024.0f), &sb, &cb);
    const float2 fbase = make_float2(cb, sb);          // e^{i pi t/1024}
    const float2 w1t   = cmul(fbase, fbase);           // e^{2pi i t/1024}
    const float2 w1_4  = cmul(cmul(w1t, w1t), cmul(w1t, w1t));
    const float2 w1_8  = cmul(w1_4, w1_4);
    const float2 w1_12 = cmul(w1_8, w1_4);

    const int p2 = t >> 4;
    float s2, c2;
    __sincosf((float)p2 * (6.283185307179586f / 64.0f), &s2, &c2);
    const float2 w2t   = make_float2(c2, s2);          // e^{2pi i p2/64}
    const float2 w2_4  = cmul(cmul(w2t, w2t), cmul(w2t, w2t));
    const float2 w2_8  = cmul(w2_4, w2_4);
    const float2 w2_12 = cmul(w2_8, w2_4);

    float2 prev0[4], prev1[4];
    #pragma unroll
    for (int e = 0; e < 4; e++) {
        prev0[e] = make_float2(0.0f, 0.0f);
        prev1[e] = make_float2(0.0f, 0.0f);
    }

    for (int tf = t_first; tf < t_start + FPB; tf++) {
        const __half2* __restrict__ X = g_spec + (size_t)(b * NF + tf) * NC;

        // ---- prologue: Hermitian fold (1/2048 normalization folded in) ----
        float2 v[16];
        const float inv = 1.0f / 2048.0f;
        #pragma unroll
        for (int j = 0; j < 16; j++) {
            int k = t + 64 * j;
            float2 Xk = __half22float2(X[k]);
            float2 Xm = __half22float2(X[1024 - k]);
            if (k == 0) { Xk.y = 0.0f; Xm.y = 0.0f; }
            float Ax = (Xk.x + Xm.x) * inv;
            float Ay = (Xk.y - Xm.y) * inv;
            float Dx = (Xk.x - Xm.x) * inv;
            float Dy = (Xk.y + Xm.y) * inv;
            float2 fw = cmul(fbase, fj_const(j));       // e^{i pi (t+64j)/1024}
            float Bx = Dx * fw.x - Dy * fw.y;
            float By = Dx * fw.y + Dy * fw.x;
            v[j] = make_float2(Ax - By, Ay + Bx);
        }

        // ---- round 1: radix-16 (s=1); layer2 fused with twiddled store ----
        dft16_layer1(v);
        {
            const int sb0 = 16 * t;
            float2 wk = w1t;                    // w1t^k0, chained
            #pragma unroll
            for (int k0 = 0; k0 < 4; k0++) {
                float2 x0, x1, x2, x3;
                radix4_inv(v[4*k0], v[4*k0+1], v[4*k0+2], v[4*k0+3], x0, x1, x2, x3);
                if (k0 == 0) {
                    buf[STAG(sb0)]      = x0;
                    buf[STAG(sb0 + 4)]  = cmul(x1, w1_4);
                    buf[STAG(sb0 + 8)]  = cmul(x2, w1_8);
                    buf[STAG(sb0 + 12)] = cmul(x3, w1_12);
                } else {
                    buf[STAG(sb0 + k0)]      = cmul(x0, wk);
                    buf[STAG(sb0 + k0 + 4)]  = cmul(x1, cmul(wk, w1_4));
                    buf[STAG(sb0 + k0 + 8)]  = cmul(x2, cmul(wk, w1_8));
                    buf[STAG(sb0 + k0 + 12)] = cmul(x3, cmul(wk, w1_12));
                    wk = cmul(wk, w1t);
                }
            }
        }
        __syncthreads();

        // ---- round 2: radix-16 (s=16), in-place read/write split ----
        #pragma unroll
        for (int j = 0; j < 16; j++)
            v[j] = buf[STAG(t + 64 * j)];
        __syncthreads();

        dft16_layer1(v);
        {
            const int base = (t & 15) + (p2 << 8);      // q + 256 p
            float2 wk = w2t;
            #pragma unroll
            for (int k0 = 0; k0 < 4; k0++) {
                float2 x0, x1, x2, x3;
                radix4_inv(v[4*k0], v[4*k0+1], v[4*k0+2], v[4*k0+3], x0, x1, x2, x3);
                if (k0 == 0) {
                    buf[STAG(base)]            = x0;
                    buf[STAG(base + 16*4)]     = cmul(x1, w2_4);
                    buf[STAG(base + 16*8)]     = cmul(x2, w2_8);
                    buf[STAG(base + 16*12)]    = cmul(x3, w2_12);
                } else {
                    buf[STAG(base + 16*k0)]        = cmul(x0, wk);
                    buf[STAG(base + 16*(k0+4))]    = cmul(x1, cmul(wk, w2_4));
                    buf[STAG(base + 16*(k0+8))]    = cmul(x2, cmul(wk, w2_8));
                    buf[STAG(base + 16*(k0+12))]   = cmul(x3, cmul(wk, w2_12));
                    wk = cmul(wk, w2t);
                }
            }
        }
        __syncthreads();

        // ---- round 3: radix-4 (s=256, p=0, twiddle 1) + OLA output ----
        const int obase = b * (NSAMP / 2) + tf * 512;
        #pragma unroll
        for (int e = 0; e < 4; e++) {
            int u3 = t + 64 * e;
            int sp = STAG(u3);
            float2 a  = buf[sp];
            float2 bb = buf[sp + 256];
            float2 c  = buf[sp + 512];
            float2 d  = buf[sp + 768];
            float2 r0, r1, r2, r3;
            radix4_inv(a, bb, c, d, r0, r1, r2, r3);
            // r0,r1: sample-pairs m=u3, u3+256 (first half of frame tf)
            // r2,r3: pairs m=u3+512, u3+768 (second half -> overlap for tf+1)
            if (tf >= t_start) {
                out2[obase + u3]       = make_float2(r0.x + prev0[e].x, r0.y + prev0[e].y);
                out2[obase + 256 + u3] = make_float2(r1.x + prev1[e].x, r1.y + prev1[e].y);
            }
            prev0[e] = r2;
            prev1[e] = r3;
        }
        __syncthreads();   // buf reused by next frame's round-1 writes
    }
}

// ---------------------------------------------------------------------------
extern "C" void kernel_launch(void* const* d_in, const int* in_sizes, int n_in,
                              void* d_out, int out_size)
{
    const float* amp   = (const float*)d_in[0];
    const float* phase = (const float*)d_in[1];
    const float* decay = (const float*)d_in[2];
    const float* dith  = (const float*)d_in[3];
    float* out = (float*)d_out;

    spec_kernel<<<(NB * NC + 255) / 256, 256>>>(amp, phase, decay, dith);
    dim3 grid2(NCHUNK, NB);
    ifft_ola_kernel<<<grid2, 64>>>((float2*)out);
}

// round 8
// speedup vs baseline: 1.4730x; 1.4730x over previous
#include <cuda_runtime.h>
#include <cuda_fp16.h>
#include <cstdint>

#define NB      256          // N_RES * EXPR flattened rows
#define NC      1025         // coeffs per row
#define NF      128          // frames
#define HOP     1024
#define NSAMP   131072
#define FPB     16           // frames per ifft block
#define NCHUNK  (NF / FPB)   // 8

// Scratch (allowed: __device__ globals, no runtime alloc)
__device__ __half2 g_spec[33587200];     // NB*NF*NC fp16 spectrum, 134MB

// ---------------------------------------------------------------------------
// Threefry-2x32 (20 rounds), JAX partitionable counter mode: key=(0,42),
// x=(0, i), output = v0 ^ v1.   (bit-verified in round 2)
// ---------------------------------------------------------------------------
__device__ __forceinline__ uint32_t threefry_xor(uint32_t x0, uint32_t x1) {
    const uint32_t ks0 = 0u, ks1 = 42u;
    const uint32_t ks2 = ks0 ^ ks1 ^ 0x1BD11BDAu;
    x0 += ks0; x1 += ks1;
#define TF_R(r) { x0 += x1; x1 = __funnelshift_l(x1, x1, (r)); x1 ^= x0; }
    TF_R(13) TF_R(15) TF_R(26) TF_R(6)
    x0 += ks1; x1 += ks2 + 1u;
    TF_R(17) TF_R(29) TF_R(16) TF_R(24)
    x0 += ks2; x1 += ks0 + 2u;
    TF_R(13) TF_R(15) TF_R(26) TF_R(6)
    x0 += ks0; x1 += ks1 + 3u;
    TF_R(17) TF_R(29) TF_R(16) TF_R(24)
    x0 += ks1; x1 += ks2 + 4u;
    TF_R(13) TF_R(15) TF_R(26) TF_R(6)
    x0 += ks2; x1 += ks0 + 5u;
#undef TF_R
    return x0 ^ x1;
}

// ---------------------------------------------------------------------------
// Kernel 1: spectrum synthesis (unchanged — at its ALU issue floor)
// ---------------------------------------------------------------------------
__global__ void __launch_bounds__(256) spec_kernel(
    const float* __restrict__ amp,   const float* __restrict__ phase,
    const float* __restrict__ decay, const float* __restrict__ dith)
{
    int gid = blockIdx.x * 256 + threadIdx.x;
    if (gid >= NB * NC) return;
    int b = gid / NC;
    int k = gid - b * NC;
    int pidx = (((b >> 2) * NC + k) << 2) + (b & 3);   // (N_RES, NC, EXPR) layout

    float a  = amp[pidx];
    float ph = phase[pidx];
    float dc = decay[pidx];
    float dt = dith[pidx];

    float sig = 1.0f / (1.0f + expf(-dc));
    float c   = 0.5f + (sig * 0.5f) * 0.99f;
    float m   = a * a;
    float sp  = tanhf(ph) * 3.14159274101257324f;
    float d   = tanhf(dt);

    uint32_t idx = (uint32_t)(b * NF) * (uint32_t)NC + (uint32_t)k;
    float acc = 0.0f;
    __half2* __restrict__ outp = g_spec + idx;

    #pragma unroll 4
    for (int t = 0; t < NF; t++) {
        uint32_t bits = threefry_xor(0u, idx);
        float u  = __uint_as_float((bits >> 9) | 0x3f800000u) - 1.0f;  // [0,1)
        float nz = fmaf(u, 2.0f, -1.0f);                               // [-1,1)
        acc += fmaf(d, nz, sp);
        m   *= c;

        float kq  = rintf(acc * 0.15915494309189535f);
        float red = fmaf(kq, -6.2831854820251465f, acc);
        red       = fmaf(kq,  1.7484555e-07f, red);
        float sn, cs;
        __sincosf(red, &sn, &cs);

        *outp = __floats2half2_rn(m * cs, m * sn);
        outp += NC;
        idx  += NC;
    }
}

// ---------------------------------------------------------------------------
// complex helpers
// ---------------------------------------------------------------------------
__device__ __forceinline__ float2 cadd(float2 a, float2 b){ return make_float2(a.x+b.x, a.y+b.y); }
__device__ __forceinline__ float2 csub(float2 a, float2 b){ return make_float2(a.x-b.x, a.y-b.y); }
__device__ __forceinline__ float2 cmul(float2 a, float2 b){
    return make_float2(a.x*b.x - a.y*b.y, a.x*b.y + a.y*b.x);
}
__device__ __forceinline__ float2 cmulc(float2 a, float cx, float cy){
    return make_float2(a.x*cx - a.y*cy, a.x*cy + a.y*cx);
}

__device__ __forceinline__ void radix4_inv(float2 a, float2 b, float2 c, float2 d,
                                           float2& t0, float2& t1, float2& t2, float2& t3)
{
    float2 apc = cadd(a, c), amc = csub(a, c);
    float2 bpd = cadd(b, d), bmd = csub(b, d);
    t0 = cadd(apc, bpd);
    t2 = csub(apc, bpd);
    t1 = make_float2(amc.x - bmd.y, amc.y + bmd.x);  // (a-c) + i(b-d)
    t3 = make_float2(amc.x + bmd.y, amc.y - bmd.x);  // (a-c) - i(b-d)
}

// Inverse 8-pt DFT (sign +i), natural order in/out, via even/odd radix-4 split.
// X[k] = E[k] + W8^k O[k];  X[k+4] = E[k] - W8^k O[k];  W8 = e^{i pi/4}.
__device__ __forceinline__ void dft8_inv(const float2 v[8], float2 X[8])
{
    const float C = 0.70710678118654752f;
    float2 E0, E1, E2, E3, O0, O1, O2, O3;
    radix4_inv(v[0], v[2], v[4], v[6], E0, E1, E2, E3);
    radix4_inv(v[1], v[3], v[5], v[7], O0, O1, O2, O3);
    X[0] = cadd(E0, O0);            X[4] = csub(E0, O0);
    float2 t1 = cmulc(O1,  C, C);   // W8^1
    X[1] = cadd(E1, t1);            X[5] = csub(E1, t1);
    float2 t2 = make_float2(-O2.y, O2.x);   // i * O2
    X[2] = cadd(E2, t2);            X[6] = csub(E2, t2);
    float2 t3 = cmulc(O3, -C, C);   // W8^3
    X[3] = cadd(E3, t3);            X[7] = csub(E3, t3);
}

// e^{i pi j/8}, j=0..7 — serves both the fold per-j factor (e^{i pi 128j/1024})
// and the stage-C twiddle W16^j = e^{2 pi i j/16}.
__device__ __constant__ float E8C[8] = { 1.0f,  0.92387953251f,  0.70710678119f,  0.38268343236f,
                                         0.0f, -0.38268343236f, -0.70710678119f, -0.92387953251f };
__device__ __constant__ float E8S[8] = { 0.0f,  0.38268343236f,  0.70710678119f,  0.92387953251f,
                                         1.0f,  0.92387953251f,  0.70710678119f,  0.38268343236f };

// Stagger: conflict-free (distinct low-4 nibbles per 16-lane phase) for all
// access patterns in this kernel; STAG8(A+512) == STAG8(A)+512.
#define STAG8(A) ((A) ^ (((A) >> 3) & 15))

// ---------------------------------------------------------------------------
// Kernel 2: fused irfft + overlap-add. 128 threads per frame pipeline,
// 8 complex values per thread. 1024 = 8*8*8*2:
//   fold -> radix-8 (regs) -> xchg -> radix-8 -> xchg -> radix-8 -> xchg
//        -> radix-2 (twiddle-free) fused with OLA output to global.
// OLA overlap carried in 4 float2 registers across the sequential frame loop.
// ---------------------------------------------------------------------------
__global__ void __launch_bounds__(128) ifft_ola_kernel(float2* __restrict__ out2)
{
    __shared__ float2 bufA[1024];
    __shared__ float2 bufB[1024];

    const int u       = threadIdx.x;          // 0..127
    const int b       = blockIdx.y;
    const int chunk   = blockIdx.x;
    const int t_start = chunk * FPB;
    const int t_first = (chunk == 0) ? 0 : t_start - 1;

    // hoisted frame-invariant twiddle bases
    float sb, cb;
    __sincosf((float)u * (3.14159265358979f / 1024.0f), &sb, &cb);
    const float2 fbase = make_float2(cb, sb);          // e^{i pi u/1024}
    const float2 w1A   = cmul(fbase, fbase);           // e^{2 pi i u/1024}
    const int    pB    = u >> 3;                       // 0..15
    float s2, c2;
    __sincosf((float)pB * (6.283185307179586f / 128.0f), &s2, &c2);
    const float2 w1B   = make_float2(c2, s2);          // e^{2 pi i pB/128}
    const int    pC    = (u >> 6) & 1;                 // warp-uniform

    float2 prev[4];
    #pragma unroll
    for (int e = 0; e < 4; e++) prev[e] = make_float2(0.0f, 0.0f);

    for (int tf = t_first; tf < t_start + FPB; tf++) {
        const __half2* __restrict__ X = g_spec + (size_t)(b * NF + tf) * NC;

        // ---- prologue: Hermitian fold (1/2048 normalization folded in) ----
        float2 v[8];
        const float inv = 1.0f / 2048.0f;
        #pragma unroll
        for (int j = 0; j < 8; j++) {
            int k = u + 128 * j;
            float2 Xk = __half22float2(X[k]);
            float2 Xm = __half22float2(X[1024 - k]);
            if (k == 0) { Xk.y = 0.0f; Xm.y = 0.0f; }
            float Ax = (Xk.x + Xm.x) * inv;
            float Ay = (Xk.y - Xm.y) * inv;
            float Dx = (Xk.x - Xm.x) * inv;
            float Dy = (Xk.y + Xm.y) * inv;
            float2 fw = cmulc(fbase, E8C[j], E8S[j]);   // e^{i pi (u+128j)/1024}
            float Bx = Dx * fw.x - Dy * fw.y;
            float By = Dx * fw.y + Dy * fw.x;
            v[j] = make_float2(Ax - By, Ay + Bx);
        }

        float2 Y[8];

        // ---- stage A: radix-8, s=1, twiddle W1024^{u k}, write 8u+k ----
        dft8_inv(v, Y);
        {
            const int ba = 8 * u;
            bufA[STAG8(ba)] = Y[0];
            float2 w = w1A;
            #pragma unroll
            for (int k = 1; k < 8; k++) {
                bufA[STAG8(ba + k)] = cmul(Y[k], w);
                if (k < 7) w = cmul(w, w1A);
            }
        }
        __syncthreads();

        // ---- stage B: radix-8, s=8, twiddle W128^{pB k} ----
        #pragma unroll
        for (int j = 0; j < 8; j++) v[j] = bufA[STAG8(u + 128 * j)];
        dft8_inv(v, Y);
        {
            const int bb = (u & 7) + 64 * pB;           // q + 64 p
            bufB[STAG8(bb)] = Y[0];
            float2 w = w1B;
            #pragma unroll
            for (int k = 1; k < 8; k++) {
                bufB[STAG8(bb + 8 * k)] = cmul(Y[k], w);
                if (k < 7) w = cmul(w, w1B);
            }
        }
        __syncthreads();

        // ---- stage C: radix-8, s=64, twiddle W16^{pC k} (constants) ----
        #pragma unroll
        for (int j = 0; j < 8; j++) v[j] = bufB[STAG8(u + 128 * j)];
        dft8_inv(v, Y);
        {
            const int bc = (u & 63) + 512 * pC;         // q + 512 p
            if (pC) {                                    // warp-uniform branch
                #pragma unroll
                for (int k = 1; k < 8; k++) Y[k] = cmulc(Y[k], E8C[k], E8S[k]);
            }
            #pragma unroll
            for (int k = 0; k < 8; k++)
                bufA[STAG8(bc + 64 * k)] = Y[k];
        }
        __syncthreads();

        // ---- stage D: radix-2, s=512, twiddle-free, fused with OLA ----
        const int obase = b * (NSAMP / 2) + tf * 512;
        #pragma unroll
        for (int e = 0; e < 4; e++) {
            int u4 = u + 128 * e;
            int sp = STAG8(u4);
            float2 a  = bufA[sp];
            float2 bb = bufA[sp + 512];                 // STAG8(u4+512)==STAG8(u4)+512
            float2 t0 = cadd(a, bb);                    // sample-pair u4 (first half)
            float2 t1 = csub(a, bb);                    // pair u4+512 (second half)
            if (tf >= t_start)
                out2[obase + u4] = make_float2(t0.x + prev[e].x, t0.y + prev[e].y);
            prev[e] = t1;
        }
        __syncthreads();   // bufA reused by next frame's stage-A writes
    }
}

// ---------------------------------------------------------------------------
extern "C" void kernel_launch(void* const* d_in, const int* in_sizes, int n_in,
                              void* d_out, int out_size)
{
    const float* amp   = (const float*)d_in[0];
    const float* phase = (const float*)d_in[1];
    const float* decay = (const float*)d_in[2];
    const float* dith  = (const float*)d_in[3];
    float* out = (float*)d_out;

    spec_kernel<<<(NB * NC + 255) / 256, 256>>>(amp, phase, decay, dith);
    dim3 grid2(NCHUNK, NB);
    ifft_ola_kernel<<<grid2, 128>>>((float2*)out);
}